// round 12
// baseline (speedup 1.0000x reference)
#include <cuda_runtime.h>
#include <stdint.h>

#define LSEQ   2048
#define DDIM   64
#define KMAX   64
#define NBUCK  4096                    // buckets per (batch, group)
#define BSLOT  8                       // slots per bucket = one 64B line
#define NSLOTS (NBUCK * BSLOT)         // 32768 slots per (batch, group)
#define SMASKS (NSLOTS - 1)
#define BSHIFT 20                      // bucket = code >> 20 (top 12 bits)
#define FIXCAP 1024

// Static device scratch (zero-init). Tables are write-idempotent across graph
// replays (same inputs -> same entry set) -> never cleared.
// Entry: (code << 32) | (idx+1); 0 = empty. Sized for <=4 batches per launch.
__device__ unsigned long long g_ktab[(size_t)4 * 2 * NSLOTS];   // key codes
__device__ unsigned long long g_qtab[(size_t)4 * 2 * NSLOTS];   // query codes
__device__ unsigned long long g_kcodes[4 * LSEQ];               // (klo<<32)|khi
__device__ unsigned int       g_done;   // monotone ticket (last-block elect)
__device__ int                g_nfix;   // fixup count (reset by last block)
__device__ int                g_fix[FIXCAP];

// Exact row rebuild for chunk-relative query gq: ballot-ordered scan of the
// packed key codes (unique ascending union of groups, first KMAX, pad -1).
__device__ __forceinline__ void rebuild_row(const float* __restrict__ qin,
                                            float* __restrict__ out,
                                            int gq, int lane) {
    const int bb = gq >> 11;
    const float* qp = qin + (size_t)gq * DDIM;
    const uint32_t qlo = __ballot_sync(0xFFFFFFFFu, qp[lane]      > 0.0f);
    const uint32_t qhi = __ballot_sync(0xFFFFFFFFu, qp[lane + 32] > 0.0f);
    float* o = out + (size_t)gq * KMAX;
    const uint32_t ltmask = (1u << lane) - 1u;
    int count = 0;
    for (int c = 0; c < LSEQ / 32; c++) {
        const int j = c * 32 + lane;
        const unsigned long long kc = g_kcodes[(bb << 11) + j];
        const bool m = ((uint32_t)(kc >> 32) == qlo) | ((uint32_t)kc == qhi);
        const uint32_t mask = __ballot_sync(0xFFFFFFFFu, m);
        if (mask) {
            const int pos = count + __popc(mask & ltmask);
            if (m && pos < KMAX) o[pos] = (float)j;
            count += __popc(mask);
            if (count >= KMAX) break;          // warp-uniform
        }
    }
    for (int p = (count < KMAX ? count : KMAX) + lane; p < KMAX; p += 32)
        o[p] = -1.0f;
}

__global__ void __launch_bounds__(256)
fused_kernel(const float* __restrict__ qin, const float* __restrict__ kin,
             float* __restrict__ out, int ntok)
{
    __shared__ int s_last;
    const int w    = (blockIdx.x * blockDim.x + threadIdx.x) >> 5;
    const int lane = threadIdx.x & 31;
    const int bb   = w >> 11;                        // batch within chunk

    // ---- Pack both tokens (coalesced 512B read + 4 ballots). ----
    const float* qp = qin + (size_t)w * DDIM;
    const float* kp = kin + (size_t)w * DDIM;
    const uint32_t qlo = __ballot_sync(0xFFFFFFFFu, qp[lane]      > 0.0f);
    const uint32_t qhi = __ballot_sync(0xFFFFFFFFu, qp[lane + 32] > 0.0f);
    const uint32_t klo = __ballot_sync(0xFFFFFFFFu, kp[lane]      > 0.0f);
    const uint32_t khi = __ballot_sync(0xFFFFFFFFu, kp[lane + 32] > 0.0f);

    if (lane == 0)
        g_kcodes[w] = ((unsigned long long)klo << 32) | khi;

    // ---- Coalesced -1.0f fill of this warp's row (32 x float2 = 256B). ----
    ((float2*)(out + (size_t)w * KMAX))[lane] = make_float2(-1.f, -1.f);

    // ---- 4 parallel idempotent inserts (lanes 0..3). ----
    if (lane < 4) {
        const bool isq = (lane >= 2);
        const int  grp = lane & 1;
        const uint32_t code = isq ? (grp ? qhi : qlo) : (grp ? khi : klo);
        unsigned long long* tab = isq ? g_qtab : g_ktab;
        const size_t tb = (size_t)(bb * 2 + grp) * NSLOTS;
        const unsigned long long v =
            ((unsigned long long)code << 32) | (uint32_t)((w & (LSEQ - 1)) + 1);
        int s = (int)(code >> BSHIFT) * BSLOT;
        while (true) {
            unsigned long long cur = tab[tb + s];
            if (cur == v) break;                     // steady state (replay)
            if (cur == 0ULL) {
                unsigned long long old = atomicCAS(&tab[tb + s], 0ULL, v);
                if (old == 0ULL || old == v) break;
            }
            s = (s + 1) & SMASKS;
        }
    }
    __syncwarp();
    __threadfence();                                 // order inserts before probes

    // ---- One flat probe round (all 32 lanes, 1 independent 8B load each).
    //      lanes 0..15 : q codes vs key-table   (side 0)
    //      lanes 16..31: k codes vs query-table (side 1) ----
    const int  side = lane >> 4;
    const int  grp  = (lane >> 3) & 1;
    const int  slot = lane & 7;
    const uint32_t pcode = side ? (grp ? khi : klo) : (grp ? qhi : qlo);
    const unsigned long long* ptab = side ? g_qtab : g_ktab;
    const unsigned long long pv =
        __ldcg(&ptab[(size_t)(bb * 2 + grp) * NSLOTS +
                     (size_t)(pcode >> BSHIFT) * BSLOT + slot]);
    const bool match = (pv != 0ULL) && ((uint32_t)(pv >> 32) == pcode);
    const bool fullb = (slot == 7) && (pv != 0ULL);  // possible bucket overflow
    const uint32_t mm = __ballot_sync(0xFFFFFFFFu, match | fullb);

    if (mm) {                                        // warp-uniform, ~never
        // side 0: any flag -> fixup(own query w); elect one lane.
        if ((mm & 0xFFFFu) && lane == (__ffs(mm & 0xFFFFu) - 1)) {
            int p = atomicAdd(&g_nfix, 1);
            if (p < FIXCAP) atomicExch(&g_fix[p], w);
        }
        // side 1 match: fixup(that query).
        if (side && match) {
            int gq = (bb << 11) + (int)((uint32_t)pv - 1);
            int p = atomicAdd(&g_nfix, 1);
            if (p < FIXCAP) atomicExch(&g_fix[p], gq);
        }
        // side 1 overflowed query-bucket: batch-wide sentinel.
        if (side && fullb && !match) {
            int p = atomicAdd(&g_nfix, 1);
            if (p < FIXCAP) atomicExch(&g_fix[p], -(bb + 2));
        }
        __threadfence();
    }

    // ---- Last-finishing block processes fixups (no co-residency needed). ----
    __syncthreads();
    if (threadIdx.x == 0) {
        __threadfence();
        unsigned int t = atomicAdd(&g_done, 1u);
        s_last = ((t % gridDim.x) == gridDim.x - 1u);
    }
    __syncthreads();

    if (s_last) {
        const int wib = threadIdx.x >> 5;            // 8 warps in block
        int n = *(volatile int*)&g_nfix;
        if (n > FIXCAP) n = FIXCAP;
        for (int i = wib; i < n; i += 8) {
            int e = *(volatile int*)&g_fix[i];
            if (e >= 0) {
                rebuild_row(qin, out, e, lane);
            } else {                                  // full-batch rescan
                int fb = -e - 2;
                for (int qq = wib; qq < LSEQ; qq += 8)   // conservative
                    rebuild_row(qin, out, (fb << 11) + qq, lane);
            }
        }
        __syncthreads();
        if (threadIdx.x == 0) { g_nfix = 0; __threadfence(); }
    }
}

extern "C" void kernel_launch(void* const* d_in, const int* in_sizes, int n_in,
                              void* d_out, int out_size) {
    const float* q = (const float*)d_in[0];
    const float* k = (const float*)d_in[1];

    int B = out_size / (LSEQ * KMAX);        // out is [B, L, KMAX] float32
    if (B < 1) B = 1;

    for (int b0 = 0; b0 < B; b0 += 4) {      // bench B=4 -> one launch
        int bl = B - b0; if (bl > 4) bl = 4;
        int ntok   = bl * LSEQ;
        int blocks = ntok / 8;               // warp per token, 8 warps/block
        fused_kernel<<<blocks, 256>>>(q + (size_t)b0 * LSEQ * DDIM,
                                      k + (size_t)b0 * LSEQ * DDIM,
                                      (float*)d_out + (size_t)b0 * LSEQ * KMAX,
                                      ntok);
    }
}

// round 13
// speedup vs baseline: 1.1140x; 1.1140x over previous
#include <cuda_runtime.h>
#include <stdint.h>

#define LSEQ   2048
#define DDIM   64
#define KMAX   64
#define NBUCK  4096                    // buckets per (batch, group)
#define BSLOT  8                       // slots per bucket = one 64B line
#define NSLOTS (NBUCK * BSLOT)
#define SMASKS (NSLOTS - 1)
#define BSHIFT 20                      // bucket = code >> 20 (top 12 bits)

// Static device scratch (zero-init). Entries are write-idempotent across
// graph replays (same inputs -> same entry set) -> never cleared.
// Entry: (code << 32) | (idx+1); 0 = empty. Sized for <=4 batches per launch.
__device__ unsigned long long g_tab[(size_t)4 * 2 * NSLOTS];
__device__ unsigned long long g_kcodes[4 * LSEQ];   // (code_g0<<32)|code_g1

// Sign nibble of a float4.
__device__ __forceinline__ uint32_t nib4(float4 v) {
    return (uint32_t)(v.x > 0.f) | ((uint32_t)(v.y > 0.f) << 1) |
           ((uint32_t)(v.z > 0.f) << 2) | ((uint32_t)(v.w > 0.f) << 3);
}
// Assemble a 32-bit group code from 4 ballots at half-warp 'base' (0/8/16/24).
// Fixed permutation of the 32 sign bits -- equality-preserving.
__device__ __forceinline__ uint32_t asm_code(uint32_t b0, uint32_t b1,
                                             uint32_t b2, uint32_t b3,
                                             int base) {
    return ((b0 >> base) & 0xFFu) | (((b1 >> base) & 0xFFu) << 8) |
           (((b2 >> base) & 0xFFu) << 16) | (((b3 >> base) & 0xFFu) << 24);
}

// Canonical code pair for one token, computed by a full warp.
// lane&15 loads float4 (dims 4h..4h+3); group g from lanes 8g..8g+7.
__device__ __forceinline__ void warp_codes(const float* __restrict__ p,
                                           int lane, uint32_t& c0, uint32_t& c1) {
    float4 v = ((const float4*)p)[lane & 15];
    uint32_t s  = nib4(v);
    uint32_t b0 = __ballot_sync(0xFFFFFFFFu, s & 1u);
    uint32_t b1 = __ballot_sync(0xFFFFFFFFu, s & 2u);
    uint32_t b2 = __ballot_sync(0xFFFFFFFFu, s & 4u);
    uint32_t b3 = __ballot_sync(0xFFFFFFFFu, s & 8u);
    c0 = asm_code(b0, b1, b2, b3, 0);
    c1 = asm_code(b0, b1, b2, b3, 8);
}

// Exact row rebuild (cold path): ballot-ordered scan of packed key codes.
__device__ void rebuild_row(const float* __restrict__ qin,
                            float* __restrict__ out, int gq, int lane) {
    const int bb = gq >> 11;
    uint32_t qlo, qhi;
    warp_codes(qin + (size_t)gq * DDIM, lane, qlo, qhi);
    float* o = out + (size_t)gq * KMAX;
    const uint32_t ltmask = (1u << lane) - 1u;
    int count = 0;
    for (int c = 0; c < LSEQ / 32; c++) {
        const int j = c * 32 + lane;
        const unsigned long long kc = g_kcodes[(bb << 11) + j];
        const bool m = ((uint32_t)(kc >> 32) == qlo) | ((uint32_t)kc == qhi);
        const uint32_t mask = __ballot_sync(0xFFFFFFFFu, m);
        if (mask) {
            const int pos = count + __popc(mask & ltmask);
            if (m && pos < KMAX) o[pos] = (float)j;
            count += __popc(mask);
            if (count >= KMAX) break;            // warp-uniform
        }
    }
    for (int p = (count < KMAX ? count : KMAX) + lane; p < KMAX; p += 32)
        o[p] = -1.0f;
}

// K1: keys. Warp handles 4 tokens via two independent float4 rounds
// (lane: r = lane>>4 selects token within pair, h = lane&15 the quarter).
// Codes staged to smem; lanes 0..7 insert concurrently (idempotent CAS).
__global__ void __launch_bounds__(256)
scatter_keys_kernel(const float* __restrict__ k, int ntok) {
    __shared__ uint32_t s_codes[8][8];           // [warp][token*2 + group]
    const int wib  = threadIdx.x >> 5;
    const int w    = (blockIdx.x * blockDim.x + threadIdx.x) >> 5;
    const int lane = threadIdx.x & 31;
    const int t0   = w * 4;
    if (t0 >= ntok) return;
    const int r = lane >> 4, h = lane & 15;

    // Two independent 512B rounds (tokens t0+r and t0+2+r).
    float4 v0 = ((const float4*)(k + (size_t)(t0 + r)     * DDIM))[h];
    float4 v1 = ((const float4*)(k + (size_t)(t0 + 2 + r) * DDIM))[h];
    uint32_t sa = nib4(v0), sb = nib4(v1);
    uint32_t A0 = __ballot_sync(0xFFFFFFFFu, sa & 1u);
    uint32_t A1 = __ballot_sync(0xFFFFFFFFu, sa & 2u);
    uint32_t A2 = __ballot_sync(0xFFFFFFFFu, sa & 4u);
    uint32_t A3 = __ballot_sync(0xFFFFFFFFu, sa & 8u);
    uint32_t B0 = __ballot_sync(0xFFFFFFFFu, sb & 1u);
    uint32_t B1 = __ballot_sync(0xFFFFFFFFu, sb & 2u);
    uint32_t B2 = __ballot_sync(0xFFFFFFFFu, sb & 4u);
    uint32_t B3 = __ballot_sync(0xFFFFFFFFu, sb & 8u);

    if (h == 0) {       // lanes 0 and 16: write codes for tokens r and r+2
        const int base = 16 * r;
        uint32_t a0 = asm_code(A0, A1, A2, A3, base);
        uint32_t a1 = asm_code(A0, A1, A2, A3, base + 8);
        uint32_t b0 = asm_code(B0, B1, B2, B3, base);
        uint32_t b1 = asm_code(B0, B1, B2, B3, base + 8);
        s_codes[wib][2 * r]           = a0;
        s_codes[wib][2 * r + 1]       = a1;
        s_codes[wib][2 * (r + 2)]     = b0;
        s_codes[wib][2 * (r + 2) + 1] = b1;
        g_kcodes[t0 + r]     = ((unsigned long long)a0 << 32) | a1;
        g_kcodes[t0 + r + 2] = ((unsigned long long)b0 << 32) | b1;
    }
    __syncwarp();

    if (lane < 8) {                              // 8 concurrent inserts
        const int tok = t0 + (lane >> 1);
        const int grp = lane & 1;
        const uint32_t code = s_codes[wib][lane];
        const int bb  = tok >> 11;
        const int idx = tok & (LSEQ - 1);
        const size_t tb = (size_t)(bb * 2 + grp) * NSLOTS;
        const unsigned long long v =
            ((unsigned long long)code << 32) | (uint32_t)(idx + 1);
        int s = (int)(code >> BSHIFT) * BSLOT;
        while (true) {
            unsigned long long cur = g_tab[tb + s];
            if (cur == v) break;                 // steady state (replay)
            if (cur == 0ULL) {
                unsigned long long old = atomicCAS(&g_tab[tb + s], 0ULL, v);
                if (old == 0ULL || old == v) break;
            }
            s = (s + 1) & SMASKS;
        }
    }
}

// K2: warp per 2 queries. Fill store issued FIRST (independent), then one
// float4 input round + 4 ballots, per-lane code assembly, one flat 32-lane
// probe (2q x 2grp x 8slot). Cold: exact rebuild per flagged query.
__global__ void __launch_bounds__(256)
probe_fill_kernel(const float* __restrict__ qin, float* __restrict__ out,
                  int ntok) {
    const int w    = (blockIdx.x * blockDim.x + threadIdx.x) >> 5;
    const int lane = threadIdx.x & 31;
    const int q0   = w * 2;
    if (q0 >= ntok) return;
    const int bb = q0 >> 11;

    // Fill first: warp's 2 rows = 128 floats = 32 float4 (512B, coalesced).
    float4* ob = (float4*)(out + (size_t)q0 * KMAX);
    ob[lane] = make_float4(-1.f, -1.f, -1.f, -1.f);

    // One 512B input round: lane r=lane>>4 -> query q0+r, h=lane&15 quarter.
    const int r = lane >> 4, h = lane & 15;
    float4 v = ((const float4*)(qin + (size_t)(q0 + r) * DDIM))[h];
    uint32_t s  = nib4(v);
    uint32_t b0 = __ballot_sync(0xFFFFFFFFu, s & 1u);
    uint32_t b1 = __ballot_sync(0xFFFFFFFFu, s & 2u);
    uint32_t b2 = __ballot_sync(0xFFFFFFFFu, s & 4u);
    uint32_t b3 = __ballot_sync(0xFFFFFFFFu, s & 8u);

    // Probe mapping: lane = 16*qsel + 8*grp + slot.
    const int qsel = lane >> 4;
    const int grp  = (lane >> 3) & 1;
    const int slot = lane & 7;
    const uint32_t pcode = asm_code(b0, b1, b2, b3, 16 * qsel + 8 * grp);
    const unsigned long long pv =
        __ldcg(&g_tab[(size_t)(bb * 2 + grp) * NSLOTS +
                      (size_t)(pcode >> BSHIFT) * BSLOT + slot]);
    const bool match = (pv != 0ULL) && ((uint32_t)(pv >> 32) == pcode);
    const bool fullb = (slot == 7) && (pv != 0ULL);   // possible overflow
    const uint32_t mm = __ballot_sync(0xFFFFFFFFu, match | fullb);

    if (mm) {                                   // warp-uniform, ~never taken
        __syncwarp();                            // order fill before rewrite
        if (mm & 0x0000FFFFu) rebuild_row(qin, out, q0,     lane);
        if (mm & 0xFFFF0000u) rebuild_row(qin, out, q0 + 1, lane);
    }
}

extern "C" void kernel_launch(void* const* d_in, const int* in_sizes, int n_in,
                              void* d_out, int out_size) {
    const float* q = (const float*)d_in[0];
    const float* k = (const float*)d_in[1];

    int B = out_size / (LSEQ * KMAX);        // out is [B, L, KMAX] float32
    if (B < 1) B = 1;

    for (int b0 = 0; b0 < B; b0 += 4) {      // bench B=4 -> one chunk
        int bl = B - b0; if (bl > 4) bl = 4;
        int ntok = bl * LSEQ;

        // K1: warp per 4 key tokens -> 256 blocks @ B=4.
        int blocks1 = ((ntok / 4) * 32 + 255) / 256;
        scatter_keys_kernel<<<blocks1, 256>>>(k + (size_t)b0 * LSEQ * DDIM, ntok);

        // K2: warp per 2 queries -> 512 blocks @ B=4.
        int blocks2 = ((ntok / 2) * 32 + 255) / 256;
        probe_fill_kernel<<<blocks2, 256>>>(q + (size_t)b0 * LSEQ * DDIM,
                                            (float*)d_out + (size_t)b0 * LSEQ * KMAX,
                                            ntok);
    }
}